// round 3
// baseline (speedup 1.0000x reference)
#include <cuda_runtime.h>

#define NBLK 96
#define NJ   21
#define FPT  63                 // floats per sample (21 joints x 3)
#define TILE (NBLK * FPT)       // 6048 floats per array per block

struct V3 { float x, y, z; };

__device__ __forceinline__ V3 mkv3(float x, float y, float z) { V3 r; r.x = x; r.y = y; r.z = z; return r; }
__device__ __forceinline__ V3 sub3(V3 a, V3 b) { return mkv3(a.x - b.x, a.y - b.y, a.z - b.z); }
__device__ __forceinline__ V3 add3(V3 a, V3 b) { return mkv3(a.x + b.x, a.y + b.y, a.z + b.z); }
__device__ __forceinline__ V3 scl3(V3 a, float s) { return mkv3(a.x * s, a.y * s, a.z * s); }
__device__ __forceinline__ float dot3(V3 a, V3 b) { return a.x * b.x + a.y * b.y + a.z * b.z; }
__device__ __forceinline__ V3 cross3(V3 a, V3 b) {
    return mkv3(a.y * b.z - a.z * b.y, a.z * b.x - a.x * b.z, a.x * b.y - a.y * b.x);
}

// Rodrigues rotation taking v0 toward v1, replicating the reference _rot_between
// (EPS = 1e-8 regularization) exactly.
struct Rot { float ax, ay, az, s, omc; };

__device__ __forceinline__ Rot makeRot(V3 v0, V3 v1) {
    float l0 = sqrtf(dot3(v0, v0));
    float i0 = 1.0f / (l0 + 1e-8f);
    float l1 = sqrtf(dot3(v1, v1));
    float i1 = 1.0f / (l1 + 1e-8f);
    V3 n0 = scl3(v0, i0);
    V3 n1 = scl3(v1, i1);
    float c = dot3(n0, n1);
    V3 ax = cross3(n0, n1);
    float s = sqrtf(dot3(ax, ax));
    float is = 1.0f / (s + 1e-8f);
    Rot r;
    r.ax = ax.x * is; r.ay = ax.y * is; r.az = ax.z * is;
    r.s = s; r.omc = 1.0f - c;
    return r;
}

// R w = w + s (k x w) + (1-c) (k x (k x w))
__device__ __forceinline__ V3 rotApply(const Rot& r, V3 w) {
    V3 a = mkv3(r.ax, r.ay, r.az);
    V3 k1 = cross3(a, w);
    V3 k2 = cross3(a, k1);
    return mkv3(w.x + r.s * k1.x + r.omc * k2.x,
                w.y + r.s * k1.y + r.omc * k2.y,
                w.z + r.s * k1.z + r.omc * k2.z);
}

// One exact Jacobi rotation on symmetric 4x4 stored as scalars (pair P,Q).
// arp1/arq1 and arp2/arq2 are A[r][P], A[r][Q] for the two other indices r.
// vXp/vXq are V[X][P], V[X][Q] (eigenvectors in columns of V).
#define JROT(app, aqq, apq, arp1, arq1, arp2, arq2, v0p, v0q, v1p, v1q, v2p, v2q, v3p, v3q) \
do {                                                                                        \
    float _apq = apq;                                                                       \
    if (_apq != 0.0f) {                                                                     \
        float _tau = (aqq - app) / (2.0f * _apq);                                           \
        float _sgn = (_tau >= 0.0f) ? 1.0f : -1.0f;                                         \
        float _tt  = _sgn / (fabsf(_tau) + sqrtf(1.0f + _tau * _tau));                      \
        float _cc  = rsqrtf(1.0f + _tt * _tt);                                              \
        float _ss  = _tt * _cc;                                                             \
        app = app - _tt * _apq;                                                             \
        aqq = aqq + _tt * _apq;                                                             \
        apq = 0.0f;                                                                         \
        float _t1, _t2;                                                                     \
        _t1 = arp1; _t2 = arq1; arp1 = _cc*_t1 - _ss*_t2; arq1 = _ss*_t1 + _cc*_t2;         \
        _t1 = arp2; _t2 = arq2; arp2 = _cc*_t1 - _ss*_t2; arq2 = _ss*_t1 + _cc*_t2;         \
        _t1 = v0p;  _t2 = v0q;  v0p  = _cc*_t1 - _ss*_t2; v0q  = _ss*_t1 + _cc*_t2;         \
        _t1 = v1p;  _t2 = v1q;  v1p  = _cc*_t1 - _ss*_t2; v1q  = _ss*_t1 + _cc*_t2;         \
        _t1 = v2p;  _t2 = v2q;  v2p  = _cc*_t1 - _ss*_t2; v2q  = _ss*_t1 + _cc*_t2;         \
        _t1 = v3p;  _t2 = v3q;  v3p  = _cc*_t1 - _ss*_t2; v3q  = _ss*_t1 + _cc*_t2;         \
    }                                                                                       \
} while (0)

__global__ void __launch_bounds__(NBLK)
kin_kernel(const float* __restrict__ jgt, const float* __restrict__ tpl,
           float* __restrict__ out, int n)
{
    __shared__ float sG[TILE];  // joint_gt tile
    __shared__ float sT[TILE];  // tempJ tile; reused as output tile

    const int tid = threadIdx.x;
    const long long base = (long long)blockIdx.x * TILE;
    const long long nF = (long long)n * FPT;
    const bool full = (base + TILE) <= nF;

    // ---- coalesced staging: gmem -> smem ----
    if (full) {
        const float4* g4 = reinterpret_cast<const float4*>(jgt + base);
        const float4* t4 = reinterpret_cast<const float4*>(tpl + base);
        float4* sG4 = reinterpret_cast<float4*>(sG);
        float4* sT4 = reinterpret_cast<float4*>(sT);
        #pragma unroll 4
        for (int k = tid; k < TILE / 4; k += NBLK) { sG4[k] = g4[k]; sT4[k] = t4[k]; }
    } else {
        for (int k = tid; k < TILE; k += NBLK) {
            long long gi = base + k;
            if (gi < nF) { sG[k] = jgt[gi]; sT[k] = tpl[gi]; }
        }
    }
    __syncthreads();

    const int samp = blockIdx.x * NBLK + tid;
    if (samp < n) {
        const int bt = tid * FPT;
        const V3 wg = mkv3(sG[bt + 0], sG[bt + 1], sG[bt + 2]);  // joint_gt wrist
        const V3 wt = mkv3(sT[bt + 0], sT[bt + 1], sT[bt + 2]);  // tempJ wrist

        // ---- H = sum_j tJ0_j * jg_j^T (j=0 term is exactly zero) ----
        float h00 = 0.f, h01 = 0.f, h02 = 0.f;
        float h10 = 0.f, h11 = 0.f, h12 = 0.f;
        float h20 = 0.f, h21 = 0.f, h22 = 0.f;
        #pragma unroll
        for (int j = 1; j < NJ; ++j) {
            float ax = sT[bt + 3 * j + 0] - wt.x;
            float ay = sT[bt + 3 * j + 1] - wt.y;
            float az = sT[bt + 3 * j + 2] - wt.z;
            float bx = sG[bt + 3 * j + 0] - wg.x;
            float by = sG[bt + 3 * j + 1] - wg.y;
            float bz = sG[bt + 3 * j + 2] - wg.z;
            h00 += ax * bx; h01 += ax * by; h02 += ax * bz;
            h10 += ay * bx; h11 += ay * by; h12 += ay * bz;
            h20 += az * bx; h21 += az * by; h22 += az * bz;
        }

        // ---- Horn 4x4 matrix N; max eigenvector = quaternion of Kabsch R ----
        float A00 = h00 + h11 + h22;
        float A01 = h12 - h21;
        float A02 = h20 - h02;
        float A03 = h01 - h10;
        float A11 = h00 - h11 - h22;
        float A12 = h01 + h10;
        float A13 = h02 + h20;
        float A22 = -h00 + h11 - h22;
        float A23 = h12 + h21;
        float A33 = -h00 - h11 + h22;

        float V00 = 1.f, V01 = 0.f, V02 = 0.f, V03 = 0.f;
        float V10 = 0.f, V11 = 1.f, V12 = 0.f, V13 = 0.f;
        float V20 = 0.f, V21 = 0.f, V22 = 1.f, V23 = 0.f;
        float V30 = 0.f, V31 = 0.f, V32 = 0.f, V33 = 1.f;

        #pragma unroll
        for (int sweep = 0; sweep < 5; ++sweep) {
            JROT(A00, A11, A01, A02, A12, A03, A13, V00, V01, V10, V11, V20, V21, V30, V31);
            JROT(A00, A22, A02, A01, A12, A03, A23, V00, V02, V10, V12, V20, V22, V30, V32);
            JROT(A00, A33, A03, A01, A13, A02, A23, V00, V03, V10, V13, V20, V23, V30, V33);
            JROT(A11, A22, A12, A01, A02, A13, A23, V01, V02, V11, V12, V21, V22, V31, V32);
            JROT(A11, A33, A13, A01, A03, A12, A23, V01, V03, V11, V13, V21, V23, V31, V33);
            JROT(A22, A33, A23, A02, A03, A12, A13, V02, V03, V12, V13, V22, V23, V32, V33);
        }

        float qw = V00, qx = V10, qy = V20, qz = V30, bd = A00;
        if (A11 > bd) { bd = A11; qw = V01; qx = V11; qy = V21; qz = V31; }
        if (A22 > bd) { bd = A22; qw = V02; qx = V12; qy = V22; qz = V32; }
        if (A33 > bd) { bd = A33; qw = V03; qx = V13; qy = V23; qz = V33; }
        float qn = rsqrtf(qw * qw + qx * qx + qy * qy + qz * qz);
        qw *= qn; qx *= qn; qy *= qn; qz *= qn;

        const float r00 = 1.f - 2.f * (qy * qy + qz * qz);
        const float r01 = 2.f * (qx * qy - qw * qz);
        const float r02 = 2.f * (qx * qz + qw * qy);
        const float r10 = 2.f * (qx * qy + qw * qz);
        const float r11 = 1.f - 2.f * (qx * qx + qz * qz);
        const float r12 = 2.f * (qy * qz - qw * qx);
        const float r20 = 2.f * (qx * qz - qw * qy);
        const float r21 = 2.f * (qy * qz + qw * qx);
        const float r22 = 1.f - 2.f * (qx * qx + qy * qy);

        // output joint 0 = wrist of joint_gt
        sT[bt + 0] = wg.x; sT[bt + 1] = wg.y; sT[bt + 2] = wg.z;

        // ---- per-finger chain: bones rotate descendants in place; final tJ == pos ----
        const int tipIdx[5] = {17, 18, 20, 19, 16};
        #pragma unroll
        for (int f = 0; f < 5; ++f) {
            const int a = 3 * f + 1;
            const int jidx[4] = {a, a + 1, a + 2, tipIdx[f]};
            V3 P[4], G[3];
            #pragma unroll
            for (int k = 0; k < 4; ++k) {
                const int j = jidx[k];
                float tx = sT[bt + 3 * j + 0] - wt.x;
                float ty = sT[bt + 3 * j + 1] - wt.y;
                float tz = sT[bt + 3 * j + 2] - wt.z;
                P[k] = mkv3(r00 * tx + r01 * ty + r02 * tz,
                            r10 * tx + r11 * ty + r12 * tz,
                            r20 * tx + r21 * ty + r22 * tz);
            }
            #pragma unroll
            for (int k = 0; k < 3; ++k) {
                const int j = jidx[k + 1];
                G[k] = mkv3(sG[bt + 3 * j + 0] - wg.x,
                            sG[bt + 3 * j + 1] - wg.y,
                            sG[bt + 3 * j + 2] - wg.z);
            }
            {   // bone 1: pivot a, child a+1; rotate {a+1, a+2, tip}
                Rot r = makeRot(sub3(P[1], P[0]), sub3(G[0], P[0]));
                P[1] = add3(rotApply(r, sub3(P[1], P[0])), P[0]);
                P[2] = add3(rotApply(r, sub3(P[2], P[0])), P[0]);
                P[3] = add3(rotApply(r, sub3(P[3], P[0])), P[0]);
            }
            {   // bone 2: pivot a+1, child a+2; rotate {a+2, tip}
                Rot r = makeRot(sub3(P[2], P[1]), sub3(G[1], P[1]));
                P[2] = add3(rotApply(r, sub3(P[2], P[1])), P[1]);
                P[3] = add3(rotApply(r, sub3(P[3], P[1])), P[1]);
            }
            {   // bone 3: pivot a+2, child tip; rotate {tip}
                Rot r = makeRot(sub3(P[3], P[2]), sub3(G[2], P[2]));
                P[3] = add3(rotApply(r, sub3(P[3], P[2])), P[2]);
            }
            #pragma unroll
            for (int k = 0; k < 4; ++k) {
                const int j = jidx[k];
                sT[bt + 3 * j + 0] = P[k].x + wg.x;
                sT[bt + 3 * j + 1] = P[k].y + wg.y;
                sT[bt + 3 * j + 2] = P[k].z + wg.z;
            }
        }
    }
    __syncthreads();

    // ---- coalesced store: smem -> gmem ----
    if (full) {
        float4* o4 = reinterpret_cast<float4*>(out + base);
        const float4* sT4 = reinterpret_cast<const float4*>(sT);
        #pragma unroll 4
        for (int k = tid; k < TILE / 4; k += NBLK) o4[k] = sT4[k];
    } else {
        for (int k = tid; k < TILE; k += NBLK) {
            long long gi = base + k;
            if (gi < nF) out[gi] = sT[k];
        }
    }
}

extern "C" void kernel_launch(void* const* d_in, const int* in_sizes, int n_in,
                              void* d_out, int out_size) {
    const float* jgt = (const float*)d_in[0];   // joint_gt [N,21,3]
    const float* tpl = (const float*)d_in[1];   // tempJ    [N,21,3]
    float* out = (float*)d_out;                 // [N,21,3] float32
    (void)n_in; (void)out_size;
    const int n = in_sizes[0] / FPT;
    const int blocks = (n + NBLK - 1) / NBLK;
    kin_kernel<<<blocks, NBLK>>>(jgt, tpl, out, n);
}

// round 6
// speedup vs baseline: 1.6232x; 1.6232x over previous
#include <cuda_runtime.h>

#define NBLK 64
#define NJ   21
#define FPT  63                 // floats per sample (21 joints x 3)
#define TILE (NBLK * FPT)       // 4032 floats per array per block

struct V3 { float x, y, z; };

__device__ __forceinline__ V3 mkv3(float x, float y, float z) { V3 r; r.x = x; r.y = y; r.z = z; return r; }
__device__ __forceinline__ V3 sub3(V3 a, V3 b) { return mkv3(a.x - b.x, a.y - b.y, a.z - b.z); }
__device__ __forceinline__ V3 add3(V3 a, V3 b) { return mkv3(a.x + b.x, a.y + b.y, a.z + b.z); }
__device__ __forceinline__ V3 scl3(V3 a, float s) { return mkv3(a.x * s, a.y * s, a.z * s); }
__device__ __forceinline__ float dot3(V3 a, V3 b) { return a.x * b.x + a.y * b.y + a.z * b.z; }
__device__ __forceinline__ V3 cross3(V3 a, V3 b) {
    return mkv3(a.y * b.z - a.z * b.y, a.z * b.x - a.x * b.z, a.x * b.y - a.y * b.x);
}

// fast sqrt: x * rsqrt(x), guarded so x==0 -> 0 (not NaN)
__device__ __forceinline__ float fsqrt_fast(float x) {
    return x * rsqrtf(fmaxf(x, 1e-30f));
}

// Rodrigues rotation taking v0 toward v1, replicating the reference _rot_between
// (EPS = 1e-8 regularization) semantics with fast intrinsics.
struct Rot { float ax, ay, az, s, omc; };

__device__ __forceinline__ Rot makeRot(V3 v0, V3 v1) {
    float d0 = dot3(v0, v0);
    float l0 = fsqrt_fast(d0);
    float i0 = __fdividef(1.0f, l0 + 1e-8f);
    float d1 = dot3(v1, v1);
    float l1 = fsqrt_fast(d1);
    float i1 = __fdividef(1.0f, l1 + 1e-8f);
    V3 n0 = scl3(v0, i0);
    V3 n1 = scl3(v1, i1);
    float c = dot3(n0, n1);
    V3 ax = cross3(n0, n1);
    float s2 = dot3(ax, ax);
    float s = fsqrt_fast(s2);
    float is = __fdividef(1.0f, s + 1e-8f);
    Rot r;
    r.ax = ax.x * is; r.ay = ax.y * is; r.az = ax.z * is;
    r.s = s; r.omc = 1.0f - c;
    return r;
}

// R w = w + s (k x w) + (1-c) (k x (k x w))
__device__ __forceinline__ V3 rotApply(const Rot& r, V3 w) {
    V3 a = mkv3(r.ax, r.ay, r.az);
    V3 k1 = cross3(a, w);
    V3 k2 = cross3(a, k1);
    return mkv3(w.x + r.s * k1.x + r.omc * k2.x,
                w.y + r.s * k1.y + r.omc * k2.y,
                w.z + r.s * k1.z + r.omc * k2.z);
}

// Division-free exact Jacobi rotation on symmetric 4x4 (pair P,Q).
//   sin2t = sgn(d)*t2*invr, cos2t = |d|*invr  (theta in [-pi/4, pi/4])
//   c = sqrt(c2v), 1/c = rsqrt(c2v), s = sin2t/(2c), tan = s/c.
// Algebraically identical to the tau/tan formulation; crit path ~48 cyc, no FDIV.
#define JROT(app, aqq, apq, arp1, arq1, arp2, arq2, v0p, v0q, v1p, v1q, v2p, v2q, v3p, v3q) \
do {                                                                                        \
    float _apq = apq;                                                                       \
    if (_apq != 0.0f) {                                                                     \
        float _t2  = 2.0f * _apq;                                                           \
        float _d   = aqq - app;                                                             \
        float _invr = rsqrtf(_t2 * _t2 + _d * _d);                                          \
        float _co  = fabsf(_d) * _invr;                                                     \
        float _c2v = 0.5f * (1.0f + _co);                                                   \
        float _ir2 = rsqrtf(_c2v);                                                          \
        float _cc  = _c2v * _ir2;                                                           \
        float _sg  = (_d >= 0.0f) ? 0.5f : -0.5f;                                           \
        float _ss  = _sg * _t2 * _invr * _ir2;                                              \
        float _tt  = _ss * _ir2;                                                            \
        app = app - _tt * _apq;                                                             \
        aqq = aqq + _tt * _apq;                                                             \
        apq = 0.0f;                                                                         \
        float _t1x, _t2x;                                                                   \
        _t1x = arp1; _t2x = arq1; arp1 = _cc*_t1x - _ss*_t2x; arq1 = _ss*_t1x + _cc*_t2x;   \
        _t1x = arp2; _t2x = arq2; arp2 = _cc*_t1x - _ss*_t2x; arq2 = _ss*_t1x + _cc*_t2x;   \
        _t1x = v0p;  _t2x = v0q;  v0p  = _cc*_t1x - _ss*_t2x; v0q  = _ss*_t1x + _cc*_t2x;   \
        _t1x = v1p;  _t2x = v1q;  v1p  = _cc*_t1x - _ss*_t2x; v1q  = _ss*_t1x + _cc*_t2x;   \
        _t1x = v2p;  _t2x = v2q;  v2p  = _cc*_t1x - _ss*_t2x; v2q  = _ss*_t1x + _cc*_t2x;   \
        _t1x = v3p;  _t2x = v3q;  v3p  = _cc*_t1x - _ss*_t2x; v3q  = _ss*_t1x + _cc*_t2x;   \
    }                                                                                       \
} while (0)

__global__ void __launch_bounds__(NBLK, 7)
kin_kernel(const float* __restrict__ jgt, const float* __restrict__ tpl,
           float* __restrict__ out, int n)
{
    __shared__ float sG[TILE];  // joint_gt tile
    __shared__ float sT[TILE];  // tempJ tile; reused as output tile

    const int tid = threadIdx.x;
    const long long base = (long long)blockIdx.x * TILE;
    const long long nF = (long long)n * FPT;
    const bool full = (base + TILE) <= nF;

    // ---- coalesced staging: gmem -> smem ----
    if (full) {
        const float4* g4 = reinterpret_cast<const float4*>(jgt + base);
        const float4* t4 = reinterpret_cast<const float4*>(tpl + base);
        float4* sG4 = reinterpret_cast<float4*>(sG);
        float4* sT4 = reinterpret_cast<float4*>(sT);
        #pragma unroll 4
        for (int k = tid; k < TILE / 4; k += NBLK) { sG4[k] = g4[k]; sT4[k] = t4[k]; }
    } else {
        for (int k = tid; k < TILE; k += NBLK) {
            long long gi = base + k;
            if (gi < nF) { sG[k] = jgt[gi]; sT[k] = tpl[gi]; }
        }
    }
    __syncthreads();

    const int samp = blockIdx.x * NBLK + tid;
    if (samp < n) {
        const int bt = tid * FPT;
        const V3 wg = mkv3(sG[bt + 0], sG[bt + 1], sG[bt + 2]);  // joint_gt wrist
        const V3 wt = mkv3(sT[bt + 0], sT[bt + 1], sT[bt + 2]);  // tempJ wrist

        // ---- H = sum_j tJ0_j * jg_j^T (j=0 term is exactly zero) ----
        float h00 = 0.f, h01 = 0.f, h02 = 0.f;
        float h10 = 0.f, h11 = 0.f, h12 = 0.f;
        float h20 = 0.f, h21 = 0.f, h22 = 0.f;
        #pragma unroll
        for (int j = 1; j < NJ; ++j) {
            float ax = sT[bt + 3 * j + 0] - wt.x;
            float ay = sT[bt + 3 * j + 1] - wt.y;
            float az = sT[bt + 3 * j + 2] - wt.z;
            float bx = sG[bt + 3 * j + 0] - wg.x;
            float by = sG[bt + 3 * j + 1] - wg.y;
            float bz = sG[bt + 3 * j + 2] - wg.z;
            h00 += ax * bx; h01 += ax * by; h02 += ax * bz;
            h10 += ay * bx; h11 += ay * by; h12 += ay * bz;
            h20 += az * bx; h21 += az * by; h22 += az * bz;
        }

        // ---- Horn 4x4 matrix N; max eigenvector = quaternion of Kabsch R ----
        float A00 = h00 + h11 + h22;
        float A01 = h12 - h21;
        float A02 = h20 - h02;
        float A03 = h01 - h10;
        float A11 = h00 - h11 - h22;
        float A12 = h01 + h10;
        float A13 = h02 + h20;
        float A22 = -h00 + h11 - h22;
        float A23 = h12 + h21;
        float A33 = -h00 - h11 + h22;

        float V00 = 1.f, V01 = 0.f, V02 = 0.f, V03 = 0.f;
        float V10 = 0.f, V11 = 1.f, V12 = 0.f, V13 = 0.f;
        float V20 = 0.f, V21 = 0.f, V22 = 1.f, V23 = 0.f;
        float V30 = 0.f, V31 = 0.f, V32 = 0.f, V33 = 1.f;

        #pragma unroll
        for (int sweep = 0; sweep < 4; ++sweep) {
            JROT(A00, A11, A01, A02, A12, A03, A13, V00, V01, V10, V11, V20, V21, V30, V31);
            JROT(A00, A22, A02, A01, A12, A03, A23, V00, V02, V10, V12, V20, V22, V30, V32);
            JROT(A00, A33, A03, A01, A13, A02, A23, V00, V03, V10, V13, V20, V23, V30, V33);
            JROT(A11, A22, A12, A01, A02, A13, A23, V01, V02, V11, V12, V21, V22, V31, V32);
            JROT(A11, A33, A13, A01, A03, A12, A23, V01, V03, V11, V13, V21, V23, V31, V33);
            JROT(A22, A33, A23, A02, A03, A12, A13, V02, V03, V12, V13, V22, V23, V32, V33);
        }

        float qw = V00, qx = V10, qy = V20, qz = V30, bd = A00;
        if (A11 > bd) { bd = A11; qw = V01; qx = V11; qy = V21; qz = V31; }
        if (A22 > bd) { bd = A22; qw = V02; qx = V12; qy = V22; qz = V32; }
        if (A33 > bd) { bd = A33; qw = V03; qx = V13; qy = V23; qz = V33; }
        float qn = rsqrtf(qw * qw + qx * qx + qy * qy + qz * qz);
        qw *= qn; qx *= qn; qy *= qn; qz *= qn;

        const float r00 = 1.f - 2.f * (qy * qy + qz * qz);
        const float r01 = 2.f * (qx * qy - qw * qz);
        const float r02 = 2.f * (qx * qz + qw * qy);
        const float r10 = 2.f * (qx * qy + qw * qz);
        const float r11 = 1.f - 2.f * (qx * qx + qz * qz);
        const float r12 = 2.f * (qy * qz - qw * qx);
        const float r20 = 2.f * (qx * qz - qw * qy);
        const float r21 = 2.f * (qy * qz + qw * qx);
        const float r22 = 1.f - 2.f * (qx * qx + qy * qy);

        // output joint 0 = wrist of joint_gt
        sT[bt + 0] = wg.x; sT[bt + 1] = wg.y; sT[bt + 2] = wg.z;

        // ---- per-finger chain: bones rotate descendants in place; final tJ == pos ----
        const int tipIdx[5] = {17, 18, 20, 19, 16};
        #pragma unroll
        for (int f = 0; f < 5; ++f) {
            const int a = 3 * f + 1;
            const int jidx[4] = {a, a + 1, a + 2, tipIdx[f]};
            V3 P[4], G[3];
            #pragma unroll
            for (int k = 0; k < 4; ++k) {
                const int j = jidx[k];
                float tx = sT[bt + 3 * j + 0] - wt.x;
                float ty = sT[bt + 3 * j + 1] - wt.y;
                float tz = sT[bt + 3 * j + 2] - wt.z;
                P[k] = mkv3(r00 * tx + r01 * ty + r02 * tz,
                            r10 * tx + r11 * ty + r12 * tz,
                            r20 * tx + r21 * ty + r22 * tz);
            }
            #pragma unroll
            for (int k = 0; k < 3; ++k) {
                const int j = jidx[k + 1];
                G[k] = mkv3(sG[bt + 3 * j + 0] - wg.x,
                            sG[bt + 3 * j + 1] - wg.y,
                            sG[bt + 3 * j + 2] - wg.z);
            }
            {   // bone 1: pivot a, child a+1; rotate {a+1, a+2, tip}
                Rot r = makeRot(sub3(P[1], P[0]), sub3(G[0], P[0]));
                P[1] = add3(rotApply(r, sub3(P[1], P[0])), P[0]);
                P[2] = add3(rotApply(r, sub3(P[2], P[0])), P[0]);
                P[3] = add3(rotApply(r, sub3(P[3], P[0])), P[0]);
            }
            {   // bone 2: pivot a+1, child a+2; rotate {a+2, tip}
                Rot r = makeRot(sub3(P[2], P[1]), sub3(G[1], P[1]));
                P[2] = add3(rotApply(r, sub3(P[2], P[1])), P[1]);
                P[3] = add3(rotApply(r, sub3(P[3], P[1])), P[1]);
            }
            {   // bone 3: pivot a+2, child tip; rotate {tip}
                Rot r = makeRot(sub3(P[3], P[2]), sub3(G[2], P[2]));
                P[3] = add3(rotApply(r, sub3(P[3], P[2])), P[2]);
            }
            #pragma unroll
            for (int k = 0; k < 4; ++k) {
                const int j = jidx[k];
                sT[bt + 3 * j + 0] = P[k].x + wg.x;
                sT[bt + 3 * j + 1] = P[k].y + wg.y;
                sT[bt + 3 * j + 2] = P[k].z + wg.z;
            }
        }
    }
    __syncthreads();

    // ---- coalesced store: smem -> gmem ----
    if (full) {
        float4* o4 = reinterpret_cast<float4*>(out + base);
        const float4* sT4 = reinterpret_cast<const float4*>(sT);
        #pragma unroll 4
        for (int k = tid; k < TILE / 4; k += NBLK) o4[k] = sT4[k];
    } else {
        for (int k = tid; k < TILE; k += NBLK) {
            long long gi = base + k;
            if (gi < nF) out[gi] = sT[k];
        }
    }
}

extern "C" void kernel_launch(void* const* d_in, const int* in_sizes, int n_in,
                              void* d_out, int out_size) {
    const float* jgt = (const float*)d_in[0];   // joint_gt [N,21,3]
    const float* tpl = (const float*)d_in[1];   // tempJ    [N,21,3]
    float* out = (float*)d_out;                 // [N,21,3] float32
    (void)n_in; (void)out_size;
    const int n = in_sizes[0] / FPT;
    const int blocks = (n + NBLK - 1) / NBLK;
    kin_kernel<<<blocks, NBLK>>>(jgt, tpl, out, n);
}

// round 7
// speedup vs baseline: 1.7870x; 1.1009x over previous
#include <cuda_runtime.h>

#define NBLK 64
#define NJ   21
#define FPT  63                 // floats per sample (21 joints x 3)
#define TILE (NBLK * FPT)       // 4032 floats per array per block

struct V3 { float x, y, z; };

__device__ __forceinline__ V3 mkv3(float x, float y, float z) { V3 r; r.x = x; r.y = y; r.z = z; return r; }
__device__ __forceinline__ V3 sub3(V3 a, V3 b) { return mkv3(a.x - b.x, a.y - b.y, a.z - b.z); }
__device__ __forceinline__ V3 add3(V3 a, V3 b) { return mkv3(a.x + b.x, a.y + b.y, a.z + b.z); }
__device__ __forceinline__ V3 scl3(V3 a, float s) { return mkv3(a.x * s, a.y * s, a.z * s); }
__device__ __forceinline__ float dot3(V3 a, V3 b) { return a.x * b.x + a.y * b.y + a.z * b.z; }
__device__ __forceinline__ V3 cross3(V3 a, V3 b) {
    return mkv3(a.y * b.z - a.z * b.y, a.z * b.x - a.x * b.z, a.x * b.y - a.y * b.x);
}

// Rodrigues rotation taking v0 toward v1. Pure-rsqrt normalization:
// 1/(||v||+1e-8) vs rsqrt(||v||^2) differ by rel 1e-8 (< fp32 ulp) for
// non-degenerate v; degenerate v gives R ~ I under both. Guards avoid inf/nan.
struct Rot { float ax, ay, az, s, omc; };

__device__ __forceinline__ Rot makeRot(V3 v0, V3 v1) {
    float i0 = rsqrtf(fmaxf(dot3(v0, v0), 1e-30f));
    float i1 = rsqrtf(fmaxf(dot3(v1, v1), 1e-30f));
    V3 n0 = scl3(v0, i0);
    V3 n1 = scl3(v1, i1);
    float c = dot3(n0, n1);
    V3 ax = cross3(n0, n1);
    float s2 = dot3(ax, ax);
    float is = rsqrtf(fmaxf(s2, 1e-30f));
    float s = s2 * is;           // = sqrt(s2), 0 when s2 == 0
    Rot r;
    r.ax = ax.x * is; r.ay = ax.y * is; r.az = ax.z * is;
    r.s = s; r.omc = 1.0f - c;
    return r;
}

// R w = w + s (k x w) + (1-c) (k x (k x w))
__device__ __forceinline__ V3 rotApply(const Rot& r, V3 w) {
    V3 a = mkv3(r.ax, r.ay, r.az);
    V3 k1 = cross3(a, w);
    V3 k2 = cross3(a, k1);
    return mkv3(w.x + r.s * k1.x + r.omc * k2.x,
                w.y + r.s * k1.y + r.omc * k2.y,
                w.z + r.s * k1.z + r.omc * k2.z);
}

// Branchless division-free exact Jacobi rotation on symmetric 4x4 (pair P,Q).
//   cos2t = |d|*invr, c^2 = (1+cos2t)/2, c = c2*rsqrt(c2), s = sgn(d)*apq*invr/c.
// Degenerate guard: if apq==0 and d==0 the pair is a 2-eigenspace; the resulting
// 45-degree mix of V columns is still a valid eigenbasis. If apq==0, d!=0 the
// rotation is exactly identity. No FDIV, no branch.
#define JROT(app, aqq, apq, arp1, arq1, arp2, arq2, v0p, v0q, v1p, v1q, v2p, v2q, v3p, v3q) \
do {                                                                                        \
    float _apq = apq;                                                                       \
    float _t2  = 2.0f * _apq;                                                               \
    float _d   = aqq - app;                                                                 \
    float _invr = rsqrtf(fmaxf(_t2 * _t2 + _d * _d, 1e-38f));                               \
    float _co  = fabsf(_d) * _invr;                                                         \
    float _c2v = 0.5f * (1.0f + _co);                                                       \
    float _ir2 = rsqrtf(_c2v);                                                              \
    float _cc  = _c2v * _ir2;                                                               \
    float _sg  = (_d >= 0.0f) ? 0.5f : -0.5f;                                               \
    float _ss  = _sg * _t2 * _invr * _ir2;                                                  \
    float _tt  = _ss * _ir2;                                                                \
    app = app - _tt * _apq;                                                                 \
    aqq = aqq + _tt * _apq;                                                                 \
    apq = 0.0f;                                                                             \
    float _t1x, _t2x;                                                                       \
    _t1x = arp1; _t2x = arq1; arp1 = _cc*_t1x - _ss*_t2x; arq1 = _ss*_t1x + _cc*_t2x;       \
    _t1x = arp2; _t2x = arq2; arp2 = _cc*_t1x - _ss*_t2x; arq2 = _ss*_t1x + _cc*_t2x;       \
    _t1x = v0p;  _t2x = v0q;  v0p  = _cc*_t1x - _ss*_t2x; v0q  = _ss*_t1x + _cc*_t2x;       \
    _t1x = v1p;  _t2x = v1q;  v1p  = _cc*_t1x - _ss*_t2x; v1q  = _ss*_t1x + _cc*_t2x;       \
    _t1x = v2p;  _t2x = v2q;  v2p  = _cc*_t1x - _ss*_t2x; v2q  = _ss*_t1x + _cc*_t2x;       \
    _t1x = v3p;  _t2x = v3q;  v3p  = _cc*_t1x - _ss*_t2x; v3q  = _ss*_t1x + _cc*_t2x;       \
} while (0)

__global__ void __launch_bounds__(NBLK, 7)
kin_kernel(const float* __restrict__ jgt, const float* __restrict__ tpl,
           float* __restrict__ out, int n)
{
    __shared__ float sG[TILE];  // joint_gt tile
    __shared__ float sT[TILE];  // tempJ tile; reused as output tile

    const int tid = threadIdx.x;
    const long long base = (long long)blockIdx.x * TILE;
    const long long nF = (long long)n * FPT;
    const bool full = (base + TILE) <= nF;

    // ---- coalesced staging: gmem -> smem ----
    if (full) {
        const float4* g4 = reinterpret_cast<const float4*>(jgt + base);
        const float4* t4 = reinterpret_cast<const float4*>(tpl + base);
        float4* sG4 = reinterpret_cast<float4*>(sG);
        float4* sT4 = reinterpret_cast<float4*>(sT);
        #pragma unroll 4
        for (int k = tid; k < TILE / 4; k += NBLK) { sG4[k] = g4[k]; sT4[k] = t4[k]; }
    } else {
        for (int k = tid; k < TILE; k += NBLK) {
            long long gi = base + k;
            if (gi < nF) { sG[k] = jgt[gi]; sT[k] = tpl[gi]; }
        }
    }
    __syncthreads();

    const int samp = blockIdx.x * NBLK + tid;
    if (samp < n) {
        const int bt = tid * FPT;
        const V3 wg = mkv3(sG[bt + 0], sG[bt + 1], sG[bt + 2]);  // joint_gt wrist
        const V3 wt = mkv3(sT[bt + 0], sT[bt + 1], sT[bt + 2]);  // tempJ wrist

        // ---- H = sum_j tJ0_j * jg_j^T (j=0 term is exactly zero) ----
        float h00 = 0.f, h01 = 0.f, h02 = 0.f;
        float h10 = 0.f, h11 = 0.f, h12 = 0.f;
        float h20 = 0.f, h21 = 0.f, h22 = 0.f;
        #pragma unroll
        for (int j = 1; j < NJ; ++j) {
            float ax = sT[bt + 3 * j + 0] - wt.x;
            float ay = sT[bt + 3 * j + 1] - wt.y;
            float az = sT[bt + 3 * j + 2] - wt.z;
            float bx = sG[bt + 3 * j + 0] - wg.x;
            float by = sG[bt + 3 * j + 1] - wg.y;
            float bz = sG[bt + 3 * j + 2] - wg.z;
            h00 += ax * bx; h01 += ax * by; h02 += ax * bz;
            h10 += ay * bx; h11 += ay * by; h12 += ay * bz;
            h20 += az * bx; h21 += az * by; h22 += az * bz;
        }

        // ---- Horn 4x4 matrix N; max eigenvector = quaternion of Kabsch R ----
        float A00 = h00 + h11 + h22;
        float A01 = h12 - h21;
        float A02 = h20 - h02;
        float A03 = h01 - h10;
        float A11 = h00 - h11 - h22;
        float A12 = h01 + h10;
        float A13 = h02 + h20;
        float A22 = -h00 + h11 - h22;
        float A23 = h12 + h21;
        float A33 = -h00 - h11 + h22;

        float V00 = 1.f, V01 = 0.f, V02 = 0.f, V03 = 0.f;
        float V10 = 0.f, V11 = 1.f, V12 = 0.f, V13 = 0.f;
        float V20 = 0.f, V21 = 0.f, V22 = 1.f, V23 = 0.f;
        float V30 = 0.f, V31 = 0.f, V32 = 0.f, V33 = 1.f;

        // Brent-Luk paired ordering: 3 stages of disjoint pairs per sweep.
        // Each stage's two rotations have independent angle chains (ILP x2);
        // result is exactly cyclic Jacobi.
        #pragma unroll
        for (int sweep = 0; sweep < 4; ++sweep) {
            // stage 1: (0,1) || (2,3)
            JROT(A00, A11, A01, A02, A12, A03, A13, V00, V01, V10, V11, V20, V21, V30, V31);
            JROT(A22, A33, A23, A02, A03, A12, A13, V02, V03, V12, V13, V22, V23, V32, V33);
            // stage 2: (0,2) || (1,3)
            JROT(A00, A22, A02, A01, A12, A03, A23, V00, V02, V10, V12, V20, V22, V30, V32);
            JROT(A11, A33, A13, A01, A03, A12, A23, V01, V03, V11, V13, V21, V23, V31, V33);
            // stage 3: (0,3) || (1,2)
            JROT(A00, A33, A03, A01, A13, A02, A23, V00, V03, V10, V13, V20, V23, V30, V33);
            JROT(A11, A22, A12, A01, A02, A13, A23, V01, V02, V11, V12, V21, V22, V31, V32);
        }

        float qw = V00, qx = V10, qy = V20, qz = V30, bd = A00;
        if (A11 > bd) { bd = A11; qw = V01; qx = V11; qy = V21; qz = V31; }
        if (A22 > bd) { bd = A22; qw = V02; qx = V12; qy = V22; qz = V32; }
        if (A33 > bd) { bd = A33; qw = V03; qx = V13; qy = V23; qz = V33; }
        float qn = rsqrtf(qw * qw + qx * qx + qy * qy + qz * qz);
        qw *= qn; qx *= qn; qy *= qn; qz *= qn;

        const float r00 = 1.f - 2.f * (qy * qy + qz * qz);
        const float r01 = 2.f * (qx * qy - qw * qz);
        const float r02 = 2.f * (qx * qz + qw * qy);
        const float r10 = 2.f * (qx * qy + qw * qz);
        const float r11 = 1.f - 2.f * (qx * qx + qz * qz);
        const float r12 = 2.f * (qy * qz - qw * qx);
        const float r20 = 2.f * (qx * qz - qw * qy);
        const float r21 = 2.f * (qy * qz + qw * qx);
        const float r22 = 1.f - 2.f * (qx * qx + qy * qy);

        // output joint 0 = wrist of joint_gt
        sT[bt + 0] = wg.x; sT[bt + 1] = wg.y; sT[bt + 2] = wg.z;

        // ---- per-finger chain: bones rotate descendants in place; final tJ == pos ----
        const int tipIdx[5] = {17, 18, 20, 19, 16};
        #pragma unroll
        for (int f = 0; f < 5; ++f) {
            const int a = 3 * f + 1;
            const int jidx[4] = {a, a + 1, a + 2, tipIdx[f]};
            V3 P[4], G[3];
            #pragma unroll
            for (int k = 0; k < 4; ++k) {
                const int j = jidx[k];
                float tx = sT[bt + 3 * j + 0] - wt.x;
                float ty = sT[bt + 3 * j + 1] - wt.y;
                float tz = sT[bt + 3 * j + 2] - wt.z;
                P[k] = mkv3(r00 * tx + r01 * ty + r02 * tz,
                            r10 * tx + r11 * ty + r12 * tz,
                            r20 * tx + r21 * ty + r22 * tz);
            }
            #pragma unroll
            for (int k = 0; k < 3; ++k) {
                const int j = jidx[k + 1];
                G[k] = mkv3(sG[bt + 3 * j + 0] - wg.x,
                            sG[bt + 3 * j + 1] - wg.y,
                            sG[bt + 3 * j + 2] - wg.z);
            }
            {   // bone 1: pivot a, child a+1; rotate {a+1, a+2, tip}
                Rot r = makeRot(sub3(P[1], P[0]), sub3(G[0], P[0]));
                P[1] = add3(rotApply(r, sub3(P[1], P[0])), P[0]);
                P[2] = add3(rotApply(r, sub3(P[2], P[0])), P[0]);
                P[3] = add3(rotApply(r, sub3(P[3], P[0])), P[0]);
            }
            {   // bone 2: pivot a+1, child a+2; rotate {a+2, tip}
                Rot r = makeRot(sub3(P[2], P[1]), sub3(G[1], P[1]));
                P[2] = add3(rotApply(r, sub3(P[2], P[1])), P[1]);
                P[3] = add3(rotApply(r, sub3(P[3], P[1])), P[1]);
            }
            {   // bone 3: pivot a+2, child tip; rotate {tip}
                Rot r = makeRot(sub3(P[3], P[2]), sub3(G[2], P[2]));
                P[3] = add3(rotApply(r, sub3(P[3], P[2])), P[2]);
            }
            #pragma unroll
            for (int k = 0; k < 4; ++k) {
                const int j = jidx[k];
                sT[bt + 3 * j + 0] = P[k].x + wg.x;
                sT[bt + 3 * j + 1] = P[k].y + wg.y;
                sT[bt + 3 * j + 2] = P[k].z + wg.z;
            }
        }
    }
    __syncthreads();

    // ---- coalesced store: smem -> gmem ----
    if (full) {
        float4* o4 = reinterpret_cast<float4*>(out + base);
        const float4* sT4 = reinterpret_cast<const float4*>(sT);
        #pragma unroll 4
        for (int k = tid; k < TILE / 4; k += NBLK) o4[k] = sT4[k];
    } else {
        for (int k = tid; k < TILE; k += NBLK) {
            long long gi = base + k;
            if (gi < nF) out[gi] = sT[k];
        }
    }
}

extern "C" void kernel_launch(void* const* d_in, const int* in_sizes, int n_in,
                              void* d_out, int out_size) {
    const float* jgt = (const float*)d_in[0];   // joint_gt [N,21,3]
    const float* tpl = (const float*)d_in[1];   // tempJ    [N,21,3]
    float* out = (float*)d_out;                 // [N,21,3] float32
    (void)n_in; (void)out_size;
    const int n = in_sizes[0] / FPT;
    const int blocks = (n + NBLK - 1) / NBLK;
    kin_kernel<<<blocks, NBLK>>>(jgt, tpl, out, n);
}

// round 8
// speedup vs baseline: 1.9046x; 1.0658x over previous
#include <cuda_runtime.h>

#define NBLK 128
#define NJ   21
#define FPT  63                 // floats per sample (21 joints x 3)
#define TILE (NBLK * FPT)       // 8064 floats per array per block
#define SMEM_BYTES (2 * TILE * (int)sizeof(float))   // 64512 B

struct V3 { float x, y, z; };

__device__ __forceinline__ V3 mkv3(float x, float y, float z) { V3 r; r.x = x; r.y = y; r.z = z; return r; }
__device__ __forceinline__ V3 sub3(V3 a, V3 b) { return mkv3(a.x - b.x, a.y - b.y, a.z - b.z); }
__device__ __forceinline__ V3 add3(V3 a, V3 b) { return mkv3(a.x + b.x, a.y + b.y, a.z + b.z); }
__device__ __forceinline__ V3 scl3(V3 a, float s) { return mkv3(a.x * s, a.y * s, a.z * s); }
__device__ __forceinline__ float dot3(V3 a, V3 b) { return a.x * b.x + a.y * b.y + a.z * b.z; }
__device__ __forceinline__ V3 cross3(V3 a, V3 b) {
    return mkv3(a.y * b.z - a.z * b.y, a.z * b.x - a.x * b.z, a.x * b.y - a.y * b.x);
}

// Rodrigues rotation taking v0 toward v1. Pure-rsqrt normalization:
// 1/(||v||+1e-8) vs rsqrt(||v||^2) differ by rel 1e-8 (< fp32 ulp) for
// non-degenerate v; degenerate v gives R ~ I under both. Guards avoid inf/nan.
struct Rot { float ax, ay, az, s, omc; };

__device__ __forceinline__ Rot makeRot(V3 v0, V3 v1) {
    float i0 = rsqrtf(fmaxf(dot3(v0, v0), 1e-30f));
    float i1 = rsqrtf(fmaxf(dot3(v1, v1), 1e-30f));
    V3 n0 = scl3(v0, i0);
    V3 n1 = scl3(v1, i1);
    float c = dot3(n0, n1);
    V3 ax = cross3(n0, n1);
    float s2 = dot3(ax, ax);
    float is = rsqrtf(fmaxf(s2, 1e-30f));
    float s = s2 * is;           // = sqrt(s2), 0 when s2 == 0
    Rot r;
    r.ax = ax.x * is; r.ay = ax.y * is; r.az = ax.z * is;
    r.s = s; r.omc = 1.0f - c;
    return r;
}

// R w = w + s (k x w) + (1-c) (k x (k x w))
__device__ __forceinline__ V3 rotApply(const Rot& r, V3 w) {
    V3 a = mkv3(r.ax, r.ay, r.az);
    V3 k1 = cross3(a, w);
    V3 k2 = cross3(a, k1);
    return mkv3(w.x + r.s * k1.x + r.omc * k2.x,
                w.y + r.s * k1.y + r.omc * k2.y,
                w.z + r.s * k1.z + r.omc * k2.z);
}

// Branchless division-free exact Jacobi rotation on symmetric 4x4 (pair P,Q).
#define JROT(app, aqq, apq, arp1, arq1, arp2, arq2, v0p, v0q, v1p, v1q, v2p, v2q, v3p, v3q) \
do {                                                                                        \
    float _apq = apq;                                                                       \
    float _t2  = 2.0f * _apq;                                                               \
    float _d   = aqq - app;                                                                 \
    float _invr = rsqrtf(fmaxf(_t2 * _t2 + _d * _d, 1e-38f));                               \
    float _co  = fabsf(_d) * _invr;                                                         \
    float _c2v = 0.5f * (1.0f + _co);                                                       \
    float _ir2 = rsqrtf(_c2v);                                                              \
    float _cc  = _c2v * _ir2;                                                               \
    float _sg  = (_d >= 0.0f) ? 0.5f : -0.5f;                                               \
    float _ss  = _sg * _t2 * _invr * _ir2;                                                  \
    float _tt  = _ss * _ir2;                                                                \
    app = app - _tt * _apq;                                                                 \
    aqq = aqq + _tt * _apq;                                                                 \
    apq = 0.0f;                                                                             \
    float _t1x, _t2x;                                                                       \
    _t1x = arp1; _t2x = arq1; arp1 = _cc*_t1x - _ss*_t2x; arq1 = _ss*_t1x + _cc*_t2x;       \
    _t1x = arp2; _t2x = arq2; arp2 = _cc*_t1x - _ss*_t2x; arq2 = _ss*_t1x + _cc*_t2x;       \
    _t1x = v0p;  _t2x = v0q;  v0p  = _cc*_t1x - _ss*_t2x; v0q  = _ss*_t1x + _cc*_t2x;       \
    _t1x = v1p;  _t2x = v1q;  v1p  = _cc*_t1x - _ss*_t2x; v1q  = _ss*_t1x + _cc*_t2x;       \
    _t1x = v2p;  _t2x = v2q;  v2p  = _cc*_t1x - _ss*_t2x; v2q  = _ss*_t1x + _cc*_t2x;       \
    _t1x = v3p;  _t2x = v3q;  v3p  = _cc*_t1x - _ss*_t2x; v3q  = _ss*_t1x + _cc*_t2x;       \
} while (0)

__global__ void __launch_bounds__(NBLK, 3)
kin_kernel(const float* __restrict__ jgt, const float* __restrict__ tpl,
           float* __restrict__ out, int n)
{
    extern __shared__ float smem_dyn[];
    float* sG = smem_dyn;          // joint_gt tile
    float* sT = smem_dyn + TILE;   // tempJ tile; reused as output tile

    const int tid = threadIdx.x;
    const long long base = (long long)blockIdx.x * TILE;
    const long long nF = (long long)n * FPT;
    const bool full = (base + TILE) <= nF;

    // ---- coalesced staging: gmem -> smem ----
    if (full) {
        const float4* g4 = reinterpret_cast<const float4*>(jgt + base);
        const float4* t4 = reinterpret_cast<const float4*>(tpl + base);
        float4* sG4 = reinterpret_cast<float4*>(sG);
        float4* sT4 = reinterpret_cast<float4*>(sT);
        #pragma unroll 4
        for (int k = tid; k < TILE / 4; k += NBLK) { sG4[k] = g4[k]; sT4[k] = t4[k]; }
    } else {
        for (int k = tid; k < TILE; k += NBLK) {
            long long gi = base + k;
            if (gi < nF) { sG[k] = jgt[gi]; sT[k] = tpl[gi]; }
        }
    }
    __syncthreads();

    const int samp = blockIdx.x * NBLK + tid;
    if (samp < n) {
        const int bt = tid * FPT;
        const V3 wg = mkv3(sG[bt + 0], sG[bt + 1], sG[bt + 2]);  // joint_gt wrist
        const V3 wt = mkv3(sT[bt + 0], sT[bt + 1], sT[bt + 2]);  // tempJ wrist

        // ---- H = sum_j tJ0_j * jg_j^T (j=0 term is exactly zero) ----
        float h00 = 0.f, h01 = 0.f, h02 = 0.f;
        float h10 = 0.f, h11 = 0.f, h12 = 0.f;
        float h20 = 0.f, h21 = 0.f, h22 = 0.f;
        #pragma unroll
        for (int j = 1; j < NJ; ++j) {
            float ax = sT[bt + 3 * j + 0] - wt.x;
            float ay = sT[bt + 3 * j + 1] - wt.y;
            float az = sT[bt + 3 * j + 2] - wt.z;
            float bx = sG[bt + 3 * j + 0] - wg.x;
            float by = sG[bt + 3 * j + 1] - wg.y;
            float bz = sG[bt + 3 * j + 2] - wg.z;
            h00 += ax * bx; h01 += ax * by; h02 += ax * bz;
            h10 += ay * bx; h11 += ay * by; h12 += ay * bz;
            h20 += az * bx; h21 += az * by; h22 += az * bz;
        }

        // ---- Horn 4x4 matrix N; max eigenvector = quaternion of Kabsch R ----
        float A00 = h00 + h11 + h22;
        float A01 = h12 - h21;
        float A02 = h20 - h02;
        float A03 = h01 - h10;
        float A11 = h00 - h11 - h22;
        float A12 = h01 + h10;
        float A13 = h02 + h20;
        float A22 = -h00 + h11 - h22;
        float A23 = h12 + h21;
        float A33 = -h00 - h11 + h22;

        float V00 = 1.f, V01 = 0.f, V02 = 0.f, V03 = 0.f;
        float V10 = 0.f, V11 = 1.f, V12 = 0.f, V13 = 0.f;
        float V20 = 0.f, V21 = 0.f, V22 = 1.f, V23 = 0.f;
        float V30 = 0.f, V31 = 0.f, V32 = 0.f, V33 = 1.f;

        // Brent-Luk paired ordering: 3 stages of disjoint pairs per sweep.
        #pragma unroll
        for (int sweep = 0; sweep < 4; ++sweep) {
            // stage 1: (0,1) || (2,3)
            JROT(A00, A11, A01, A02, A12, A03, A13, V00, V01, V10, V11, V20, V21, V30, V31);
            JROT(A22, A33, A23, A02, A03, A12, A13, V02, V03, V12, V13, V22, V23, V32, V33);
            // stage 2: (0,2) || (1,3)
            JROT(A00, A22, A02, A01, A12, A03, A23, V00, V02, V10, V12, V20, V22, V30, V32);
            JROT(A11, A33, A13, A01, A03, A12, A23, V01, V03, V11, V13, V21, V23, V31, V33);
            // stage 3: (0,3) || (1,2)
            JROT(A00, A33, A03, A01, A13, A02, A23, V00, V03, V10, V13, V20, V23, V30, V33);
            JROT(A11, A22, A12, A01, A02, A13, A23, V01, V02, V11, V12, V21, V22, V31, V32);
        }

        float qw = V00, qx = V10, qy = V20, qz = V30, bd = A00;
        if (A11 > bd) { bd = A11; qw = V01; qx = V11; qy = V21; qz = V31; }
        if (A22 > bd) { bd = A22; qw = V02; qx = V12; qy = V22; qz = V32; }
        if (A33 > bd) { bd = A33; qw = V03; qx = V13; qy = V23; qz = V33; }
        float qn = rsqrtf(qw * qw + qx * qx + qy * qy + qz * qz);
        qw *= qn; qx *= qn; qy *= qn; qz *= qn;

        const float r00 = 1.f - 2.f * (qy * qy + qz * qz);
        const float r01 = 2.f * (qx * qy - qw * qz);
        const float r02 = 2.f * (qx * qz + qw * qy);
        const float r10 = 2.f * (qx * qy + qw * qz);
        const float r11 = 1.f - 2.f * (qx * qx + qz * qz);
        const float r12 = 2.f * (qy * qz - qw * qx);
        const float r20 = 2.f * (qx * qz - qw * qy);
        const float r21 = 2.f * (qy * qz + qw * qx);
        const float r22 = 1.f - 2.f * (qx * qx + qy * qy);

        // output joint 0 = wrist of joint_gt
        sT[bt + 0] = wg.x; sT[bt + 1] = wg.y; sT[bt + 2] = wg.z;

        // ---- per-finger chain: bones rotate descendants in place; final tJ == pos ----
        const int tipIdx[5] = {17, 18, 20, 19, 16};
        #pragma unroll
        for (int f = 0; f < 5; ++f) {
            const int a = 3 * f + 1;
            const int jidx[4] = {a, a + 1, a + 2, tipIdx[f]};
            V3 P[4], G[3];
            #pragma unroll
            for (int k = 0; k < 4; ++k) {
                const int j = jidx[k];
                float tx = sT[bt + 3 * j + 0] - wt.x;
                float ty = sT[bt + 3 * j + 1] - wt.y;
                float tz = sT[bt + 3 * j + 2] - wt.z;
                P[k] = mkv3(r00 * tx + r01 * ty + r02 * tz,
                            r10 * tx + r11 * ty + r12 * tz,
                            r20 * tx + r21 * ty + r22 * tz);
            }
            #pragma unroll
            for (int k = 0; k < 3; ++k) {
                const int j = jidx[k + 1];
                G[k] = mkv3(sG[bt + 3 * j + 0] - wg.x,
                            sG[bt + 3 * j + 1] - wg.y,
                            sG[bt + 3 * j + 2] - wg.z);
            }
            {   // bone 1: pivot a, child a+1; rotate {a+1, a+2, tip}
                Rot r = makeRot(sub3(P[1], P[0]), sub3(G[0], P[0]));
                P[1] = add3(rotApply(r, sub3(P[1], P[0])), P[0]);
                P[2] = add3(rotApply(r, sub3(P[2], P[0])), P[0]);
                P[3] = add3(rotApply(r, sub3(P[3], P[0])), P[0]);
            }
            {   // bone 2: pivot a+1, child a+2; rotate {a+2, tip}
                Rot r = makeRot(sub3(P[2], P[1]), sub3(G[1], P[1]));
                P[2] = add3(rotApply(r, sub3(P[2], P[1])), P[1]);
                P[3] = add3(rotApply(r, sub3(P[3], P[1])), P[1]);
            }
            {   // bone 3: pivot a+2, child tip; rotate {tip}
                Rot r = makeRot(sub3(P[3], P[2]), sub3(G[2], P[2]));
                P[3] = add3(rotApply(r, sub3(P[3], P[2])), P[2]);
            }
            #pragma unroll
            for (int k = 0; k < 4; ++k) {
                const int j = jidx[k];
                sT[bt + 3 * j + 0] = P[k].x + wg.x;
                sT[bt + 3 * j + 1] = P[k].y + wg.y;
                sT[bt + 3 * j + 2] = P[k].z + wg.z;
            }
        }
    }
    __syncthreads();

    // ---- coalesced store: smem -> gmem ----
    if (full) {
        float4* o4 = reinterpret_cast<float4*>(out + base);
        const float4* sT4 = reinterpret_cast<const float4*>(sT);
        #pragma unroll 4
        for (int k = tid; k < TILE / 4; k += NBLK) o4[k] = sT4[k];
    } else {
        for (int k = tid; k < TILE; k += NBLK) {
            long long gi = base + k;
            if (gi < nF) out[gi] = sT[k];
        }
    }
}

extern "C" void kernel_launch(void* const* d_in, const int* in_sizes, int n_in,
                              void* d_out, int out_size) {
    const float* jgt = (const float*)d_in[0];   // joint_gt [N,21,3]
    const float* tpl = (const float*)d_in[1];   // tempJ    [N,21,3]
    float* out = (float*)d_out;                 // [N,21,3] float32
    (void)n_in; (void)out_size;

    static bool attr_set = false;               // idempotent attribute config (not state
    if (!attr_set) {                            // affecting work/output — same launch always)
        cudaFuncSetAttribute(kin_kernel, cudaFuncAttributeMaxDynamicSharedMemorySize, SMEM_BYTES);
        attr_set = true;
    }

    const int n = in_sizes[0] / FPT;
    const int blocks = (n + NBLK - 1) / NBLK;
    kin_kernel<<<blocks, NBLK, SMEM_BYTES>>>(jgt, tpl, out, n);
}